// round 1
// baseline (speedup 1.0000x reference)
#include <cuda_runtime.h>

#define B_    32768
#define W_    5
#define L_    20
#define CE_   32
#define OC_   30
#define WE_   50
#define HID_  100
#define TAGS_ 36
#define FEAT_ 400          // (WE+OC)*W
#define TPOS  18           // L - K + 1
#define S_    16           // samples per fc block

// 52.4 MB scratch for per-sample feature vectors (allocation-guard-safe device global)
__device__ float g_feats[B_ * FEAT_];

// ---------------- packed fp32x2 helpers (Blackwell FFMA2) ----------------
__device__ __forceinline__ unsigned long long ffma2(unsigned long long a,
                                                    unsigned long long b,
                                                    unsigned long long c) {
    unsigned long long d;
    asm("fma.rn.f32x2 %0, %1, %2, %3;" : "=l"(d) : "l"(a), "l"(b), "l"(c));
    return d;
}
__device__ __forceinline__ unsigned long long pack2(float lo, float hi) {
    unsigned long long r;
    asm("mov.b64 %0, {%1, %2};"
        : "=l"(r) : "r"(__float_as_uint(lo)), "r"(__float_as_uint(hi)));
    return r;
}
__device__ __forceinline__ void unpack2(unsigned long long v, float& lo, float& hi) {
    unsigned int a, b;
    asm("mov.b64 {%0, %1}, %2;" : "=r"(a), "=r"(b) : "l"(v));
    lo = __uint_as_float(a);
    hi = __uint_as_float(b);
}

// ---------------- Kernel 1: char conv + maxpool + word-emb gather ----------------
// One warp per word. lane = output channel (0..29). Channel dim is paired for FFMA2:
// acc[t] holds (sum over even-ce-of-pair, sum over odd-ce-of-pair); folded at the end.
__global__ __launch_bounds__(256, 2)
void conv_kernel(const int* __restrict__ inp,
                 const float* __restrict__ wemb,
                 const float* __restrict__ cemb,
                 const float* __restrict__ convw,
                 const float* __restrict__ convb)
{
    __shared__ __align__(16) float ce_tab[100 * CE_];    // char embedding table, 12.8 KB
    __shared__ __align__(16) float w_sh[3][32][36];      // [k][oc][ce], ce padded 32->36
    __shared__ float b_sh[32];

    const int tid = threadIdx.x;

    for (int i = tid; i < 100 * CE_; i += 256) ce_tab[i] = cemb[i];
    // conv_w given as [oc][ce][k]; transpose to [k][oc][ce] (ce contiguous for pair loads)
    for (int i = tid; i < OC_ * CE_ * 3; i += 256) {
        int oc = i / (CE_ * 3);
        int r  = i - oc * (CE_ * 3);
        int ce = r / 3;
        int k  = r - ce * 3;
        w_sh[k][oc][ce] = convw[i];
    }
    if (tid < 32) b_sh[tid] = (tid < OC_) ? convb[tid] : 0.0f;
    __syncthreads();

    const int warp = tid >> 5;
    const int lane = tid & 31;
    const int gw   = blockIdx.x * 8 + warp;      // global word index, = b*W + wi
    const int b    = gw / W_;
    const int wi   = gw - b * W_;
    const int* __restrict__ row = inp + gw * (1 + L_);

    // char ids -> float-index offsets into ce_tab (broadcast LDG, same addr warp-wide)
    int off[L_];
#pragma unroll
    for (int l = 0; l < L_; ++l) off[l] = row[1 + l] * CE_;

    const int oc = lane;                          // lanes 30,31 compute garbage, discarded
    unsigned long long acc[TPOS];
#pragma unroll
    for (int t = 0; t < TPOS; ++t) acc[t] = 0ull;

    for (int c4 = 0; c4 < CE_ / 4; ++c4) {        // 8 iterations over ce blocks of 4
        const int c0 = c4 * 4;
        const ulonglong2 w0 = *(const ulonglong2*)&w_sh[0][oc][c0];
        const ulonglong2 w1 = *(const ulonglong2*)&w_sh[1][oc][c0];
        const ulonglong2 w2 = *(const ulonglong2*)&w_sh[2][oc][c0];
#pragma unroll
        for (int l = 0; l < L_; ++l) {
            const ulonglong2 x2 = *(const ulonglong2*)&ce_tab[off[l] + c0];
            if (l < TPOS) {                       // k = 0, t = l
                acc[l] = ffma2(x2.x, w0.x, acc[l]);
                acc[l] = ffma2(x2.y, w0.y, acc[l]);
            }
            if (l >= 1 && (l - 1) < TPOS) {       // k = 1, t = l-1
                acc[l - 1] = ffma2(x2.x, w1.x, acc[l - 1]);
                acc[l - 1] = ffma2(x2.y, w1.y, acc[l - 1]);
            }
            if (l >= 2) {                         // k = 2, t = l-2 (always < TPOS)
                acc[l - 2] = ffma2(x2.x, w2.x, acc[l - 2]);
                acc[l - 2] = ffma2(x2.y, w2.y, acc[l - 2]);
            }
        }
    }

    float* __restrict__ fout = g_feats + b * FEAT_ + wi * (WE_ + OC_);

    if (lane < OC_) {
        float m = -1e30f;
#pragma unroll
        for (int t = 0; t < TPOS; ++t) {
            float a, c;
            unpack2(acc[t], a, c);
            m = fmaxf(m, a + c);
        }
        fout[WE_ + lane] = m + b_sh[lane];
    }

    // word embedding gather (all 32 lanes)
    const int wid = row[0];
    const float* __restrict__ er = wemb + wid * WE_;
    for (int j = lane; j < WE_; j += 32) fout[j] = er[j];
}

// ---------------- Kernel 2: fc1 + tanh + out ----------------
// 16 samples per block. Thread j computes h[j] for all 16 samples:
// fc1_w row read once per block per element (16x weight reuse), feats from smem
// transposed [k][s] so 4x LDS.128 yields 8 aligned sample-pairs for FFMA2.
__global__ __launch_bounds__(128, 4)
void fc_kernel(const float* __restrict__ fc1w, const float* __restrict__ fc1b,
               const float* __restrict__ outw, const float* __restrict__ outb,
               float* __restrict__ out)
{
    __shared__ __align__(16) float fsh[FEAT_ * 20];   // [k][s], s padded 16->20 (32 KB)
    __shared__ float hsh[S_][HID_ + 4];

    const int tid = threadIdx.x;
    const int s0  = blockIdx.x * S_;

    for (int i = tid; i < S_ * FEAT_; i += 128) {
        int s = i / FEAT_;
        int k = i - s * FEAT_;
        fsh[k * 20 + s] = g_feats[(s0 + s) * FEAT_ + k];
    }
    __syncthreads();

    const int j = tid;
    if (j < HID_) {
        unsigned long long acc[8];
#pragma unroll
        for (int p = 0; p < 8; ++p) acc[p] = 0ull;

        const float* __restrict__ wr = fc1w + j * FEAT_;
#pragma unroll 4
        for (int k = 0; k < FEAT_; ++k) {
            const float w = wr[k];
            const unsigned long long w2 = pack2(w, w);
            const ulonglong2* fp = (const ulonglong2*)&fsh[k * 20];
            const ulonglong2 fa = fp[0];
            const ulonglong2 fb = fp[1];
            acc[0] = ffma2(fa.x, w2, acc[0]);
            acc[1] = ffma2(fa.y, w2, acc[1]);
            acc[2] = ffma2(fb.x, w2, acc[2]);
            acc[3] = ffma2(fb.y, w2, acc[3]);
            const ulonglong2 fc = fp[2];
            const ulonglong2 fd = fp[3];
            acc[4] = ffma2(fc.x, w2, acc[4]);
            acc[5] = ffma2(fc.y, w2, acc[5]);
            acc[6] = ffma2(fd.x, w2, acc[6]);
            acc[7] = ffma2(fd.y, w2, acc[7]);
        }

        const float bb = fc1b[j];
#pragma unroll
        for (int p = 0; p < 8; ++p) {
            float a, c;
            unpack2(acc[p], a, c);
            hsh[2 * p + 0][j] = tanhf(a + bb);
            hsh[2 * p + 1][j] = tanhf(c + bb);
        }
    }
    __syncthreads();

    // output layer: flat loop over (sample, tag) pairs
    for (int pr = tid; pr < S_ * TAGS_; pr += 128) {
        const int s   = pr / TAGS_;
        const int tag = pr - s * TAGS_;
        float a = outb[tag];
        const float* __restrict__ owr = outw + tag * HID_;
#pragma unroll 4
        for (int jj = 0; jj < HID_; ++jj) a += hsh[s][jj] * owr[jj];
        out[(s0 + s) * TAGS_ + tag] = a;
    }
}

// ---------------- launch ----------------
extern "C" void kernel_launch(void* const* d_in, const int* in_sizes, int n_in,
                              void* d_out, int out_size)
{
    const int*   inp   = (const int*)  d_in[0];
    const float* wemb  = (const float*)d_in[1];
    const float* cemb  = (const float*)d_in[2];
    const float* convw = (const float*)d_in[3];
    const float* convb = (const float*)d_in[4];
    const float* fc1w  = (const float*)d_in[5];
    const float* fc1b  = (const float*)d_in[6];
    const float* outw  = (const float*)d_in[7];
    const float* outb  = (const float*)d_in[8];
    float* out = (float*)d_out;

    conv_kernel<<<(B_ * W_) / 8, 256>>>(inp, wemb, cemb, convw, convb);
    fc_kernel<<<B_ / S_, 128>>>(fc1w, fc1b, outw, outb, out);
}

// round 2
// speedup vs baseline: 1.4957x; 1.4957x over previous
#include <cuda_runtime.h>

#define B_    32768
#define W_    5
#define L_    20
#define CE_   32
#define OC_   30
#define WE_   50
#define HID_  100
#define TAGS_ 36
#define FEAT_ 400          // (WE+OC)*W
#define TPOS  18           // L - K + 1

// 52.4 MB scratch for per-sample feature vectors
__device__ float g_feats[B_ * FEAT_];

// ---------------- packed fp32x2 helpers (Blackwell FFMA2) ----------------
__device__ __forceinline__ unsigned long long ffma2(unsigned long long a,
                                                    unsigned long long b,
                                                    unsigned long long c) {
    unsigned long long d;
    asm("fma.rn.f32x2 %0, %1, %2, %3;" : "=l"(d) : "l"(a), "l"(b), "l"(c));
    return d;
}
__device__ __forceinline__ unsigned long long pack2(float lo, float hi) {
    unsigned long long r;
    asm("mov.b64 %0, {%1, %2};"
        : "=l"(r) : "r"(__float_as_uint(lo)), "r"(__float_as_uint(hi)));
    return r;
}
__device__ __forceinline__ void unpack2(unsigned long long v, float& lo, float& hi) {
    unsigned int a, b;
    asm("mov.b64 {%0, %1}, %2;" : "=r"(a), "=r"(b) : "l"(v));
    lo = __uint_as_float(a);
    hi = __uint_as_float(b);
}

// ---------------- Kernel 1: char conv + maxpool + word-emb gather ----------------
// One warp per word, lane = output channel. FFMA2 pairs over channel dim.
// Reordered so consecutive FFMA2s never target the same accumulator.
__global__ __launch_bounds__(256, 3)
void conv_kernel(const int* __restrict__ inp,
                 const float* __restrict__ wemb,
                 const float* __restrict__ cemb,
                 const float* __restrict__ convw,
                 const float* __restrict__ convb)
{
    __shared__ __align__(16) float ce_tab[100 * CE_];    // 12.8 KB
    __shared__ __align__(16) float w_sh[3][32][36];      // [k][oc][ce] (ce padded)
    __shared__ float b_sh[32];
    __shared__ int   off_sh[8][L_];                      // per-warp char offsets

    const int tid  = threadIdx.x;
    const int warp = tid >> 5;
    const int lane = tid & 31;

    for (int i = tid; i < 100 * CE_; i += 256) ce_tab[i] = cemb[i];
    for (int i = tid; i < OC_ * CE_ * 3; i += 256) {
        int oc = i / (CE_ * 3);
        int r  = i - oc * (CE_ * 3);
        int ce = r / 3;
        int k  = r - ce * 3;
        w_sh[k][oc][ce] = convw[i];
    }
    if (tid < 32) b_sh[tid] = (tid < OC_) ? convb[tid] : 0.0f;

    const int gw = blockIdx.x * 8 + warp;                // global word index = b*W + wi
    const int* __restrict__ row = inp + gw * (1 + L_);
    if (lane < L_) off_sh[warp][lane] = row[1 + lane] * CE_;
    __syncthreads();

    const int oc = lane;
    unsigned long long acc[TPOS];
#pragma unroll
    for (int t = 0; t < TPOS; ++t) acc[t] = 0ull;

#pragma unroll
    for (int c4 = 0; c4 < CE_ / 4; ++c4) {
        const int c0 = c4 * 4;
        const ulonglong2 w0 = *(const ulonglong2*)&w_sh[0][oc][c0];
        const ulonglong2 w1 = *(const ulonglong2*)&w_sh[1][oc][c0];
        const ulonglong2 w2 = *(const ulonglong2*)&w_sh[2][oc][c0];
#pragma unroll
        for (int l = 0; l < L_; ++l) {
            const ulonglong2 x2 = *(const ulonglong2*)&ce_tab[off_sh[warp][l] + c0];
            // interleave distinct accumulators: same-acc ops 3 instrs apart
            if (l < TPOS)            acc[l]     = ffma2(x2.x, w0.x, acc[l]);
            if (l >= 1 && l <= TPOS) acc[l - 1] = ffma2(x2.x, w1.x, acc[l - 1]);
            if (l >= 2)              acc[l - 2] = ffma2(x2.x, w2.x, acc[l - 2]);
            if (l < TPOS)            acc[l]     = ffma2(x2.y, w0.y, acc[l]);
            if (l >= 1 && l <= TPOS) acc[l - 1] = ffma2(x2.y, w1.y, acc[l - 1]);
            if (l >= 2)              acc[l - 2] = ffma2(x2.y, w2.y, acc[l - 2]);
        }
    }

    const int b  = gw / W_;
    const int wi = gw - b * W_;
    float* __restrict__ fout = g_feats + b * FEAT_ + wi * (WE_ + OC_);

    if (lane < OC_) {
        float m = -1e30f;
#pragma unroll
        for (int t = 0; t < TPOS; ++t) {
            float a, c;
            unpack2(acc[t], a, c);
            m = fmaxf(m, a + c);
        }
        fout[WE_ + lane] = m + b_sh[lane];
    }
    const int wid = row[0];
    const float* __restrict__ er = wemb + wid * WE_;
    for (int j = lane; j < WE_; j += 32) fout[j] = er[j];
}

// ---------------- Kernel 2: fc1 + tanh + out (tiled GEMM) ----------------
// Block: 224 threads, 64-sample tile. Compute threads (tid<200): jg=tid>>3 (4 j's),
// sg=tid&7 (8 samples). K chunked by 40; fc1_w chunk + feats staged in smem.
#define MT  64
#define KC  40
#define FPAD 72     // fsh row stride (floats)
#define WROW 100    // wsh row stride

__global__ __launch_bounds__(224, 4)
void fc_kernel(const float* __restrict__ fc1w, const float* __restrict__ fc1b,
               const float* __restrict__ outw, const float* __restrict__ outb,
               float* __restrict__ out)
{
    // pool reused: phase A = fsh[KC][FPAD] + wsh[KC][WROW]; phase B = hsh[MT][104]
    __shared__ __align__(16) float pool[KC * FPAD + KC * WROW];   // 6880 floats
    __shared__ __align__(16) float ow_sh[TAGS_ * 104];            // outw, row-padded

    float* fsh = pool;
    float* wsh = pool + KC * FPAD;
    float* hsh = pool;            // [MT][104], 6656 floats, reused after main loop

    const int tid = threadIdx.x;
    const int s0  = blockIdx.x * MT;

    // stage outw once: [tag][j] rows padded to 104 (coalesced read + write)
    for (int i = tid; i < TAGS_ * HID_; i += 224) {
        int tag = i / HID_;
        int jj  = i - tag * HID_;
        ow_sh[tag * 104 + jj] = outw[i];
    }

    const int jg = tid >> 3;          // 0..24
    const int sg = tid & 7;           // 0..7
    const int j0 = jg * 4;
    const int sb = sg * 8;
    const bool active = (tid < 200);

    unsigned long long acc[16];
#pragma unroll
    for (int p = 0; p < 16; ++p) acc[p] = 0ull;

    for (int kc = 0; kc < FEAT_ / KC; ++kc) {
        const int k0 = kc * KC;
        __syncthreads();
        // feats chunk: read coalesced (k fast), write [k][s]
        for (int i = tid; i < KC * MT; i += 224) {
            int k = i % KC;
            int s = i / KC;
            fsh[k * FPAD + s] = g_feats[(s0 + s) * FEAT_ + k0 + k];
        }
        // weight chunk: read coalesced (k fast), write [k][j]
        for (int i = tid; i < KC * HID_; i += 224) {
            int k = i % KC;
            int j = i / KC;
            wsh[k * WROW + j] = fc1w[j * FEAT_ + k0 + k];
        }
        __syncthreads();

        if (active) {
#pragma unroll 4
            for (int k = 0; k < KC; ++k) {
                const float4 wq = *(const float4*)&wsh[k * WROW + j0];
                const ulonglong2 fa = *(const ulonglong2*)&fsh[k * FPAD + sb];
                const ulonglong2 fb = *(const ulonglong2*)&fsh[k * FPAD + sb + 4];
                const unsigned long long w0 = pack2(wq.x, wq.x);
                const unsigned long long w1 = pack2(wq.y, wq.y);
                const unsigned long long w2 = pack2(wq.z, wq.z);
                const unsigned long long w3 = pack2(wq.w, wq.w);
                acc[0]  = ffma2(fa.x, w0, acc[0]);
                acc[4]  = ffma2(fa.x, w1, acc[4]);
                acc[8]  = ffma2(fa.x, w2, acc[8]);
                acc[12] = ffma2(fa.x, w3, acc[12]);
                acc[1]  = ffma2(fa.y, w0, acc[1]);
                acc[5]  = ffma2(fa.y, w1, acc[5]);
                acc[9]  = ffma2(fa.y, w2, acc[9]);
                acc[13] = ffma2(fa.y, w3, acc[13]);
                acc[2]  = ffma2(fb.x, w0, acc[2]);
                acc[6]  = ffma2(fb.x, w1, acc[6]);
                acc[10] = ffma2(fb.x, w2, acc[10]);
                acc[14] = ffma2(fb.x, w3, acc[14]);
                acc[3]  = ffma2(fb.y, w0, acc[3]);
                acc[7]  = ffma2(fb.y, w1, acc[7]);
                acc[11] = ffma2(fb.y, w2, acc[11]);
                acc[15] = ffma2(fb.y, w3, acc[15]);
            }
        }
    }
    __syncthreads();   // everyone done reading fsh/wsh before hsh overwrite

    if (active) {
#pragma unroll
        for (int jj = 0; jj < 4; ++jj) {
            const float bb = fc1b[j0 + jj];
#pragma unroll
            for (int p = 0; p < 4; ++p) {
                float a, c;
                unpack2(acc[jj * 4 + p], a, c);
                hsh[(sb + 2 * p + 0) * 104 + j0 + jj] = tanhf(a + bb);
                hsh[(sb + 2 * p + 1) * 104 + j0 + jj] = tanhf(c + bb);
            }
        }
    }
    __syncthreads();

    // out layer: pr -> (s, tag); tag fast => hsh broadcast, ow_sh coalesced
    for (int pr = tid; pr < MT * TAGS_; pr += 224) {
        const int s   = pr / TAGS_;
        const int tag = pr - s * TAGS_;
        const ulonglong2* hp = (const ulonglong2*)&hsh[s * 104];
        const ulonglong2* wp = (const ulonglong2*)&ow_sh[tag * 104];
        unsigned long long a0 = 0ull, a1 = 0ull;
#pragma unroll
        for (int q = 0; q < HID_ / 4; ++q) {
            const ulonglong2 h2 = hp[q];
            const ulonglong2 w2 = wp[q];
            a0 = ffma2(h2.x, w2.x, a0);
            a1 = ffma2(h2.y, w2.y, a1);
        }
        float x0, x1, y0, y1;
        unpack2(a0, x0, x1);
        unpack2(a1, y0, y1);
        out[(s0 + s) * TAGS_ + tag] = outb[tag] + ((x0 + y0) + (x1 + y1));
    }
}

// ---------------- launch ----------------
extern "C" void kernel_launch(void* const* d_in, const int* in_sizes, int n_in,
                              void* d_out, int out_size)
{
    const int*   inp   = (const int*)  d_in[0];
    const float* wemb  = (const float*)d_in[1];
    const float* cemb  = (const float*)d_in[2];
    const float* convw = (const float*)d_in[3];
    const float* convb = (const float*)d_in[4];
    const float* fc1w  = (const float*)d_in[5];
    const float* fc1b  = (const float*)d_in[6];
    const float* outw  = (const float*)d_in[7];
    const float* outb  = (const float*)d_in[8];
    float* out = (float*)d_out;

    conv_kernel<<<(B_ * W_) / 8, 256>>>(inp, wemb, cemb, convw, convb);
    fc_kernel<<<B_ / MT, 224>>>(fc1w, fc1b, outw, outb, out);
}

// round 3
// speedup vs baseline: 3.2040x; 2.1422x over previous
#include <cuda_runtime.h>

#define B_    32768
#define W_    5
#define L_    20
#define CE_   32
#define OC_   30
#define WE_   50
#define HID_  100
#define TAGS_ 36
#define FEAT_ 400
#define TPOS  18

__device__ float g_feats[B_ * FEAT_];
__device__ float g_P[100 * 120 + 32];     // P[c][oc][k], oc<30, k in 0..3 (k=3 pad)

// ---------------- packed fp32x2 helpers ----------------
__device__ __forceinline__ unsigned long long ffma2(unsigned long long a,
                                                    unsigned long long b,
                                                    unsigned long long c) {
    unsigned long long d;
    asm("fma.rn.f32x2 %0, %1, %2, %3;" : "=l"(d) : "l"(a), "l"(b), "l"(c));
    return d;
}
__device__ __forceinline__ unsigned long long pack2(float lo, float hi) {
    unsigned long long r;
    asm("mov.b64 %0, {%1, %2};"
        : "=l"(r) : "r"(__float_as_uint(lo)), "r"(__float_as_uint(hi)));
    return r;
}
__device__ __forceinline__ void unpack2(unsigned long long v, float& lo, float& hi) {
    unsigned int a, b;
    asm("mov.b64 {%0, %1}, %2;" : "=r"(a), "=r"(b) : "l"(v));
    lo = __uint_as_float(a);
    hi = __uint_as_float(b);
}

// ---------------- Kernel 0: precompute P[c][oc][k] = sum_ce w[oc][ce][k]*cemb[c][ce] ----
__global__ void prep_kernel(const float* __restrict__ cemb,
                            const float* __restrict__ convw)
{
    const int i = blockIdx.x * 256 + threadIdx.x;    // (c, oc) pair
    if (i >= 100 * OC_) return;
    const int c  = i / OC_;
    const int oc = i - c * OC_;
    float s0 = 0.f, s1 = 0.f, s2 = 0.f;
    const float* wr = convw + oc * (CE_ * 3);
    const float* er = cemb + c * CE_;
#pragma unroll
    for (int ce = 0; ce < CE_; ++ce) {
        const float e = er[ce];
        s0 = fmaf(wr[ce * 3 + 0], e, s0);
        s1 = fmaf(wr[ce * 3 + 1], e, s1);
        s2 = fmaf(wr[ce * 3 + 2], e, s2);
    }
    float* p = g_P + c * 120 + oc * 4;
    p[0] = s0; p[1] = s1; p[2] = s2; p[3] = 0.f;
}

// ---------------- Kernel 1: table-lookup conv + maxpool + word-emb gather ----------
// One warp per word, 16 words per warp. lane = output channel.
__global__ __launch_bounds__(256, 4)
void conv_kernel(const int* __restrict__ inp,
                 const float* __restrict__ wemb,
                 const float* __restrict__ convb)
{
    __shared__ __align__(16) float P_sh[100 * 120 + 32];   // 48.1 KB
    __shared__ float b_sh[32];

    const int tid  = threadIdx.x;
    const int warp = tid >> 5;
    const int lane = tid & 31;

    for (int i = tid; i < 100 * 120 + 32; i += 256) P_sh[i] = g_P[i];
    if (tid < 32) b_sh[tid] = (tid < OC_) ? convb[tid] : 0.0f;
    __syncthreads();

    const int ocx = (lane < OC_) ? lane : 0;   // lanes 30,31 compute discard values

    for (int it = 0; it < 16; ++it) {
        const int gw = blockIdx.x * 128 + it * 8 + warp;   // word index = b*W + wi
        const int* __restrict__ row = inp + gw * (1 + L_);
        const int v = (lane < 1 + L_) ? row[lane] : 0;

        float acc[TPOS];
#pragma unroll
        for (int t = 0; t < TPOS; ++t) acc[t] = 0.f;

#pragma unroll
        for (int l = 0; l < L_; ++l) {
            const int c = __shfl_sync(0xffffffffu, v, l + 1);
            const float4 x = *(const float4*)&P_sh[c * 120 + ocx * 4];
            if (l < TPOS)               acc[l]     += x.x;   // k=0
            if (l >= 1 && l <= TPOS)    acc[l - 1] += x.y;   // k=1
            if (l >= 2)                 acc[l - 2] += x.z;   // k=2
        }

        float m = acc[0];
#pragma unroll
        for (int t = 1; t < TPOS; ++t) m = fmaxf(m, acc[t]);

        const int b  = gw / W_;
        const int wi = gw - b * W_;
        float* __restrict__ fout = g_feats + b * FEAT_ + wi * (WE_ + OC_);

        if (lane < OC_) fout[WE_ + lane] = m + b_sh[lane];

        const int wid = __shfl_sync(0xffffffffu, v, 0);
        const float* __restrict__ er = wemb + wid * WE_;
        if (lane < WE_ - 32) fout[32 + lane] = er[32 + lane];
        fout[lane] = er[lane];
    }
}

// ---------------- Kernel 2: fc1 + tanh + out (tiled GEMM, duplicated weights) ------
#define MT   64
#define KC   20
#define FPAD 72

__global__ __launch_bounds__(224, 4)
void fc_kernel(const float* __restrict__ fc1w, const float* __restrict__ fc1b,
               const float* __restrict__ outw, const float* __restrict__ outb,
               float* __restrict__ out)
{
    // phase A: fsh[KC][FPAD] (1440) + wsh[KC][200] (4000) ; phase B: hsh[64][104] (6656)
    __shared__ __align__(16) float pool[6656];
    __shared__ __align__(16) float ow_sh[TAGS_ * 104];

    float* fsh = pool;
    float* wsh = pool + KC * FPAD;
    float* hsh = pool;

    const int tid = threadIdx.x;
    const int s0  = blockIdx.x * MT;

    for (int i = tid; i < TAGS_ * HID_; i += 224) {
        int tag = i / HID_;
        int jj  = i - tag * HID_;
        ow_sh[tag * 104 + jj] = outw[i];
    }

    const int jg = tid >> 3;           // 0..24
    const int sg = tid & 7;            // 0..7
    const int j0 = jg * 4;
    const int sb = sg * 8;
    const bool active = (tid < 200);

    unsigned long long acc[16];
#pragma unroll
    for (int p = 0; p < 16; ++p) acc[p] = 0ull;

    for (int kc = 0; kc < FEAT_ / KC; ++kc) {
        const int k0 = kc * KC;
        __syncthreads();
        // feats chunk [k][s]
        for (int i = tid; i < KC * MT; i += 224) {
            int k = i % KC;
            int s = i / KC;
            fsh[k * FPAD + s] = g_feats[(s0 + s) * FEAT_ + k0 + k];
        }
        // weight chunk, duplicated: wsh[k][2j]=wsh[k][2j+1]=w
        for (int i = tid; i < KC * HID_; i += 224) {
            int k = i % KC;
            int j = i / KC;
            const float w = fc1w[j * FEAT_ + k0 + k];
            *(unsigned long long*)&wsh[k * 200 + 2 * j] = pack2(w, w);
        }
        __syncthreads();

        if (active) {
#pragma unroll
            for (int k = 0; k < KC; ++k) {
                const ulonglong2 wa = *(const ulonglong2*)&wsh[k * 200 + 2 * j0];
                const ulonglong2 wb = *(const ulonglong2*)&wsh[k * 200 + 2 * j0 + 4];
                const ulonglong2 fa = *(const ulonglong2*)&fsh[k * FPAD + sb];
                const ulonglong2 fb = *(const ulonglong2*)&fsh[k * FPAD + sb + 4];
                acc[0]  = ffma2(fa.x, wa.x, acc[0]);
                acc[4]  = ffma2(fa.x, wa.y, acc[4]);
                acc[8]  = ffma2(fa.x, wb.x, acc[8]);
                acc[12] = ffma2(fa.x, wb.y, acc[12]);
                acc[1]  = ffma2(fa.y, wa.x, acc[1]);
                acc[5]  = ffma2(fa.y, wa.y, acc[5]);
                acc[9]  = ffma2(fa.y, wb.x, acc[9]);
                acc[13] = ffma2(fa.y, wb.y, acc[13]);
                acc[2]  = ffma2(fb.x, wa.x, acc[2]);
                acc[6]  = ffma2(fb.x, wa.y, acc[6]);
                acc[10] = ffma2(fb.x, wb.x, acc[10]);
                acc[14] = ffma2(fb.x, wb.y, acc[14]);
                acc[3]  = ffma2(fb.y, wa.x, acc[3]);
                acc[7]  = ffma2(fb.y, wa.y, acc[7]);
                acc[11] = ffma2(fb.y, wb.x, acc[11]);
                acc[15] = ffma2(fb.y, wb.y, acc[15]);
            }
        }
    }
    __syncthreads();

    if (active) {
#pragma unroll
        for (int jj = 0; jj < 4; ++jj) {
            const float bb = fc1b[j0 + jj];
#pragma unroll
            for (int p = 0; p < 4; ++p) {
                float a, c;
                unpack2(acc[jj * 4 + p], a, c);
                hsh[(sb + 2 * p + 0) * 104 + j0 + jj] = tanhf(a + bb);
                hsh[(sb + 2 * p + 1) * 104 + j0 + jj] = tanhf(c + bb);
            }
        }
    }
    __syncthreads();

    for (int pr = tid; pr < MT * TAGS_; pr += 224) {
        const int s   = pr / TAGS_;
        const int tag = pr - s * TAGS_;
        const ulonglong2* hp = (const ulonglong2*)&hsh[s * 104];
        const ulonglong2* wp = (const ulonglong2*)&ow_sh[tag * 104];
        unsigned long long a0 = 0ull, a1 = 0ull;
#pragma unroll
        for (int q = 0; q < HID_ / 4; ++q) {
            const ulonglong2 h2 = hp[q];
            const ulonglong2 w2 = wp[q];
            a0 = ffma2(h2.x, w2.x, a0);
            a1 = ffma2(h2.y, w2.y, a1);
        }
        float x0, x1, y0, y1;
        unpack2(a0, x0, x1);
        unpack2(a1, y0, y1);
        out[(s0 + s) * TAGS_ + tag] = outb[tag] + ((x0 + y0) + (x1 + y1));
    }
}

// ---------------- launch ----------------
extern "C" void kernel_launch(void* const* d_in, const int* in_sizes, int n_in,
                              void* d_out, int out_size)
{
    const int*   inp   = (const int*)  d_in[0];
    const float* wemb  = (const float*)d_in[1];
    const float* cemb  = (const float*)d_in[2];
    const float* convw = (const float*)d_in[3];
    const float* convb = (const float*)d_in[4];
    const float* fc1w  = (const float*)d_in[5];
    const float* fc1b  = (const float*)d_in[6];
    const float* outw  = (const float*)d_in[7];
    const float* outb  = (const float*)d_in[8];
    float* out = (float*)d_out;

    prep_kernel<<<(100 * OC_ + 255) / 256, 256>>>(cemb, convw);
    conv_kernel<<<(B_ * W_) / 128, 256>>>(inp, wemb, convb);
    fc_kernel<<<B_ / MT, 224>>>(fc1w, fc1b, outw, outb, out);
}